// round 1
// baseline (speedup 1.0000x reference)
#include <cuda_runtime.h>
#include <math.h>

#define LCH 64
#define NTH 64

// shared-memory float offsets
#define OFF_QS   0            // qT [64 d][64 i]  (4096) overlaid later by S [64 i][65 j] (4160)
#define OFF_KT   4160         // kT [64 d][64 j]  (4096)
#define OFF_SV   8256         // sv [64 j][68]    (4352)
#define OFF_SLF  12608
#define OFF_SG   12672
#define OFF_SB   12736
#define OFF_SA   12800
#define OFF_SENC 12864
#define OFF_SFAC 12928
#define OFF_RED  12992        // [64][8]
#define SMEM_FLOATS 13504
#define SMEM_BYTES  (SMEM_FLOATS * 4)

__global__ void __launch_bounds__(NTH) mlstm_intra_kernel(
    const float* __restrict__ q, const float* __restrict__ k,
    const float* __restrict__ v, const float* __restrict__ ig,
    const float* __restrict__ fg, float* __restrict__ out)
{
    extern __shared__ float sm[];
    float* qT   = sm + OFF_QS;
    float* S    = sm + OFF_QS;   // overlays qT after GEMM1
    float* kT   = sm + OFF_KT;
    float* sv   = sm + OFF_SV;
    float* slf  = sm + OFF_SLF;
    float* sg   = sm + OFF_SG;
    float* sb   = sm + OFF_SB;
    float* sa   = sm + OFF_SA;
    float* senc = sm + OFF_SENC;
    float* sfac = sm + OFF_SFAC;
    float* red  = sm + OFF_RED;

    const int t  = threadIdx.x;
    const int ty = t >> 3;
    const int tx = t & 7;
    const size_t base = (size_t)blockIdx.x * (LCH * 64);
    const int grow = blockIdx.x * LCH;

    // ---- load tiles: thread t owns row t; q,k transposed to d-major ----
    {
        const float4* q4 = reinterpret_cast<const float4*>(q + base + t * 64);
        const float4* k4 = reinterpret_cast<const float4*>(k + base + t * 64);
        const float4* v4 = reinterpret_cast<const float4*>(v + base + t * 64);
        float4* sv4 = reinterpret_cast<float4*>(sv + t * 68);
#pragma unroll
        for (int c = 0; c < 16; ++c) {
            float4 wq = q4[c];
            float4 wk = k4[c];
            float4 wv = v4[c];
            int d = 4 * c;
            qT[(d + 0) * 64 + t] = wq.x;
            qT[(d + 1) * 64 + t] = wq.y;
            qT[(d + 2) * 64 + t] = wq.z;
            qT[(d + 3) * 64 + t] = wq.w;
            kT[(d + 0) * 64 + t] = wk.x;
            kT[(d + 1) * 64 + t] = wk.y;
            kT[(d + 2) * 64 + t] = wk.z;
            kT[(d + 3) * 64 + t] = wk.w;
            sv4[c] = wv;
        }
    }

    // ---- gates: log_sigmoid, cumsum, prefix-max, rank-1 decay factors ----
    float xi;
    {
        float xf = fg[grow + t];
        xi = ig[grow + t];
        slf[t] = fminf(xf, 0.0f) - log1pf(__expf(-fabsf(xf)));
    }
    __syncthreads();

    float cum = 0.0f;
#pragma unroll 8
    for (int j = 0; j < LCH; ++j) {
        float lv = slf[j];
        if (j <= t) cum += lv;
    }
    float gval = xi - cum;           // g[t] = ig[t] - cum[t]
    sg[t] = gval;
    senc[t] = __expf(-cum);          // exp(-cum[t])
    __syncthreads();

    float M = -INFINITY;
#pragma unroll 8
    for (int j = 0; j < LCH; ++j) {
        float gv = sg[j];
        if (j <= t) M = fmaxf(M, gv);
    }
    sa[t] = __expf(-M);              // a[i] = exp(-M[i])
    sb[t] = __expf(gval) * 0.125f;   // b[j]*scale, scale = 1/sqrt(64)
    __syncthreads();

    // ---- GEMM1: S'[i][j] = (q[i].k[j]) (scaled/masked in epilogue) ----
    float acc[8][8];
#pragma unroll
    for (int r = 0; r < 8; ++r)
#pragma unroll
        for (int c = 0; c < 8; ++c) acc[r][c] = 0.0f;

#pragma unroll 2
    for (int d = 0; d < 64; ++d) {
        float4 a0 = *reinterpret_cast<const float4*>(qT + d * 64 + ty * 8);
        float4 a1 = *reinterpret_cast<const float4*>(qT + d * 64 + ty * 8 + 4);
        float4 b0 = *reinterpret_cast<const float4*>(kT + d * 64 + tx * 8);
        float4 b1 = *reinterpret_cast<const float4*>(kT + d * 64 + tx * 8 + 4);
        float av[8] = {a0.x, a0.y, a0.z, a0.w, a1.x, a1.y, a1.z, a1.w};
        float bv[8] = {b0.x, b0.y, b0.z, b0.w, b1.x, b1.y, b1.z, b1.w};
#pragma unroll
        for (int r = 0; r < 8; ++r)
#pragma unroll
            for (int c = 0; c < 8; ++c)
                acc[r][c] = fmaf(av[r], bv[c], acc[r][c]);
    }
    __syncthreads();   // all qT reads done; S may overwrite

    // ---- epilogue: mask, scale by b[j], store S (rotated cols), row sums ----
    const int colshift = 2 * ty;   // rotation keyed to row-group, consistent on read
    {
        float bloc[8];
#pragma unroll
        for (int c = 0; c < 8; ++c) bloc[c] = sb[tx * 8 + c];
#pragma unroll
        for (int r = 0; r < 8; ++r) {
            int i = ty * 8 + r;
            float rsum = 0.0f;
#pragma unroll
            for (int c = 0; c < 8; ++c) {
                int j = tx * 8 + c;
                float val = (j <= i) ? acc[r][c] * bloc[c] : 0.0f;
                S[i * 65 + ((j + colshift) & 63)] = val;
                rsum += val;
            }
            red[i * 8 + tx] = rsum;
        }
    }
    __syncthreads();

    // ---- per-row normalizer: n = a*max(|rs|, exp(-cum)); fac = a/(n+eps) ----
    {
        float rs = 0.0f;
#pragma unroll
        for (int x = 0; x < 8; ++x) rs += red[t * 8 + x];
        float t1 = fmaxf(fabsf(rs), senc[t]);
        float a_ = sa[t];
        sfac[t] = a_ / fmaf(a_, t1, 1e-6f);
    }
    __syncthreads();

    // ---- GEMM2: H[i][d] = sum_j S'[i][j] * v[j][d] ----
    float acc2[8][8];
#pragma unroll
    for (int r = 0; r < 8; ++r)
#pragma unroll
        for (int c = 0; c < 8; ++c) acc2[r][c] = 0.0f;

#pragma unroll 2
    for (int j = 0; j < 64; ++j) {
        int jp = (j + colshift) & 63;
        float4 b0 = *reinterpret_cast<const float4*>(sv + j * 68 + tx * 8);
        float4 b1 = *reinterpret_cast<const float4*>(sv + j * 68 + tx * 8 + 4);
        float av[8];
#pragma unroll
        for (int r = 0; r < 8; ++r) av[r] = S[(ty * 8 + r) * 65 + jp];
        float bv[8] = {b0.x, b0.y, b0.z, b0.w, b1.x, b1.y, b1.z, b1.w};
#pragma unroll
        for (int r = 0; r < 8; ++r)
#pragma unroll
            for (int c = 0; c < 8; ++c)
                acc2[r][c] = fmaf(av[r], bv[c], acc2[r][c]);
    }

    // ---- scaled output, float4 coalesced ----
#pragma unroll
    for (int r = 0; r < 8; ++r) {
        int i = ty * 8 + r;
        float f = sfac[i];
        float4 o0 = make_float4(acc2[r][0] * f, acc2[r][1] * f,
                                acc2[r][2] * f, acc2[r][3] * f);
        float4 o1 = make_float4(acc2[r][4] * f, acc2[r][5] * f,
                                acc2[r][6] * f, acc2[r][7] * f);
        *reinterpret_cast<float4*>(out + base + i * 64 + tx * 8)     = o0;
        *reinterpret_cast<float4*>(out + base + i * 64 + tx * 8 + 4) = o1;
    }
}

extern "C" void kernel_launch(void* const* d_in, const int* in_sizes, int n_in,
                              void* d_out, int out_size)
{
    const float* q  = (const float*)d_in[0];
    const float* k  = (const float*)d_in[1];
    const float* v  = (const float*)d_in[2];
    const float* ig = (const float*)d_in[3];
    const float* fg = (const float*)d_in[4];
    float* out = (float*)d_out;

    int nchunks = in_sizes[0] / (LCH * 64);   // B*NH*S*DH / (L*DH) = 2048

    cudaFuncSetAttribute(mlstm_intra_kernel,
                         cudaFuncAttributeMaxDynamicSharedMemorySize, SMEM_BYTES);
    mlstm_intra_kernel<<<nchunks, NTH, SMEM_BYTES>>>(q, k, v, ig, fg, out);
}

// round 2
// speedup vs baseline: 1.0704x; 1.0704x over previous
#include <cuda_runtime.h>
#include <math.h>

#define LCH 64
#define NTH 256

// shared-memory float offsets
#define OFF_QS   0            // qT [64 d][64 i] (4096), overlaid by S [64 i][65] (4160)
#define OFF_KT   4160         // kT [64 d][64 j] (4096)
#define OFF_SV   8256         // sv [64 j][68]   (4352)
#define OFF_SLF  12608
#define OFF_SG   12672
#define OFF_SB   12736
#define OFF_SA   12800
#define OFF_SENC 12864
#define OFF_SFAC 12928
#define OFF_RED  12992        // [64][16]
#define SMEM_FLOATS 14016
#define SMEM_BYTES  (SMEM_FLOATS * 4)

typedef unsigned long long u64;

__device__ __forceinline__ u64 dup2(float x) {
    u64 r; asm("mov.b64 %0, {%1, %1};" : "=l"(r) : "f"(x)); return r;
}
__device__ __forceinline__ void fma2(u64& d, u64 a, u64 b) {
    asm("fma.rn.f32x2 %0, %1, %2, %0;" : "+l"(d) : "l"(a), "l"(b));
}
__device__ __forceinline__ float2 unpk(u64 x) {
    float2 f; asm("mov.b64 {%0, %1}, %2;" : "=f"(f.x), "=f"(f.y) : "l"(x)); return f;
}

__global__ void __launch_bounds__(NTH, 4) mlstm_intra_kernel(
    const float* __restrict__ q, const float* __restrict__ k,
    const float* __restrict__ v, const float* __restrict__ ig,
    const float* __restrict__ fg, float* __restrict__ out)
{
    extern __shared__ float sm[];
    float* qT   = sm + OFF_QS;
    float* S    = sm + OFF_QS;   // overlays qT after GEMM1
    float* kT   = sm + OFF_KT;
    float* sv   = sm + OFF_SV;
    float* slf  = sm + OFF_SLF;
    float* sg   = sm + OFF_SG;
    float* sb   = sm + OFF_SB;
    float* sa   = sm + OFF_SA;
    float* senc = sm + OFF_SENC;
    float* sfac = sm + OFF_SFAC;
    float* red  = sm + OFF_RED;

    const int t   = threadIdx.x;
    const int ty  = t >> 4;        // 0..15 -> rows i = ty*4..ty*4+3
    const int tx  = t & 15;        // 0..15 -> cols j = tx*4..tx*4+3
    const int row = t & 63;        // load-phase row
    const int prt = t >> 6;        // load-phase quarter (0..3)
    const size_t base = (size_t)blockIdx.x * (LCH * 64);
    const int grow = blockIdx.x * LCH;

    // ---- load tiles: 256 threads, each loads 16 floats of row `row` ----
    {
        const float4* q4 = reinterpret_cast<const float4*>(q + base + row * 64 + prt * 16);
        const float4* k4 = reinterpret_cast<const float4*>(k + base + row * 64 + prt * 16);
        const float4* v4 = reinterpret_cast<const float4*>(v + base + row * 64 + prt * 16);
        float4* sv4 = reinterpret_cast<float4*>(sv + row * 68 + prt * 16);
#pragma unroll
        for (int c = 0; c < 4; ++c) {
            float4 wq = q4[c];
            float4 wk = k4[c];
            int d = prt * 16 + 4 * c;
            qT[(d + 0) * 64 + row] = wq.x;
            qT[(d + 1) * 64 + row] = wq.y;
            qT[(d + 2) * 64 + row] = wq.z;
            qT[(d + 3) * 64 + row] = wq.w;
            kT[(d + 0) * 64 + row] = wk.x;
            kT[(d + 1) * 64 + row] = wk.y;
            kT[(d + 2) * 64 + row] = wk.z;
            kT[(d + 3) * 64 + row] = wk.w;
            sv4[c] = v4[c];
        }
    }

    // ---- gates (threads 0..63): log_sigmoid, cumsum, prefix-max ----
    float xi = 0.0f;
    if (t < LCH) {
        float xf = fg[grow + t];
        xi = ig[grow + t];
        slf[t] = fminf(xf, 0.0f) - log1pf(__expf(-fabsf(xf)));
    }
    __syncthreads();

    if (t < LCH) {
        float cum = 0.0f;
#pragma unroll 8
        for (int j = 0; j < LCH; ++j) {
            float lv = slf[j];
            if (j <= t) cum += lv;
        }
        float gval = xi - cum;
        sg[t] = gval;
        senc[t] = __expf(-cum);
        sb[t] = __expf(gval) * 0.125f;   // b[j]*scale, scale = 1/sqrt(64)
    }
    __syncthreads();

    if (t < LCH) {
        float M = -INFINITY;
#pragma unroll 8
        for (int j = 0; j < LCH; ++j) {
            float gv = sg[j];
            if (j <= t) M = fmaxf(M, gv);
        }
        sa[t] = __expf(-M);              // a[i] = exp(-M[i])
    }
    __syncthreads();

    // ---- GEMM1: S'[i][j] = q[i].k[j], f32x2 packed FMA ----
    u64 acc[4][2];
#pragma unroll
    for (int r = 0; r < 4; ++r) { acc[r][0] = 0ull; acc[r][1] = 0ull; }

#pragma unroll 4
    for (int d = 0; d < 64; ++d) {
        float4 a4 = *reinterpret_cast<const float4*>(qT + d * 64 + ty * 4);
        ulonglong2 b2 = *reinterpret_cast<const ulonglong2*>(kT + d * 64 + tx * 4);
        u64 ad0 = dup2(a4.x), ad1 = dup2(a4.y), ad2 = dup2(a4.z), ad3 = dup2(a4.w);
        fma2(acc[0][0], ad0, b2.x); fma2(acc[0][1], ad0, b2.y);
        fma2(acc[1][0], ad1, b2.x); fma2(acc[1][1], ad1, b2.y);
        fma2(acc[2][0], ad2, b2.x); fma2(acc[2][1], ad2, b2.y);
        fma2(acc[3][0], ad3, b2.x); fma2(acc[3][1], ad3, b2.y);
    }
    __syncthreads();   // all qT reads done; S may overwrite

    // ---- epilogue: mask, scale by b[j], store S, partial row sums ----
    {
        float bl0 = sb[tx * 4 + 0], bl1 = sb[tx * 4 + 1];
        float bl2 = sb[tx * 4 + 2], bl3 = sb[tx * 4 + 3];
#pragma unroll
        for (int r = 0; r < 4; ++r) {
            int i = ty * 4 + r;
            float2 p0 = unpk(acc[r][0]);
            float2 p1 = unpk(acc[r][1]);
            int j0 = tx * 4;
            float v0 = (j0 + 0 <= i) ? p0.x * bl0 : 0.0f;
            float v1 = (j0 + 1 <= i) ? p0.y * bl1 : 0.0f;
            float v2 = (j0 + 2 <= i) ? p1.x * bl2 : 0.0f;
            float v3 = (j0 + 3 <= i) ? p1.y * bl3 : 0.0f;
            S[i * 65 + j0 + 0] = v0;
            S[i * 65 + j0 + 1] = v1;
            S[i * 65 + j0 + 2] = v2;
            S[i * 65 + j0 + 3] = v3;
            red[i * 16 + tx] = (v0 + v1) + (v2 + v3);
        }
    }
    __syncthreads();

    // ---- normalizer (threads 0..63): n = max(|rowsum|, exp(-m)) ----
    if (t < LCH) {
        float rs = 0.0f;
#pragma unroll
        for (int x = 0; x < 16; ++x) rs += red[t * 16 + x];
        float t1 = fmaxf(fabsf(rs), senc[t]);
        float a_ = sa[t];
        sfac[t] = a_ / fmaf(a_, t1, 1e-6f);
    }
    __syncthreads();

    // ---- GEMM2: H[i][d] = sum_j S'[i][j] * v[j][d] ----
    u64 acc2[4][2];
#pragma unroll
    for (int r = 0; r < 4; ++r) { acc2[r][0] = 0ull; acc2[r][1] = 0ull; }

#pragma unroll 4
    for (int j = 0; j < 64; ++j) {
        ulonglong2 b2 = *reinterpret_cast<const ulonglong2*>(sv + j * 68 + tx * 4);
        u64 a0 = dup2(S[(ty * 4 + 0) * 65 + j]);
        u64 a1 = dup2(S[(ty * 4 + 1) * 65 + j]);
        u64 a2 = dup2(S[(ty * 4 + 2) * 65 + j]);
        u64 a3 = dup2(S[(ty * 4 + 3) * 65 + j]);
        fma2(acc2[0][0], a0, b2.x); fma2(acc2[0][1], a0, b2.y);
        fma2(acc2[1][0], a1, b2.x); fma2(acc2[1][1], a1, b2.y);
        fma2(acc2[2][0], a2, b2.x); fma2(acc2[2][1], a2, b2.y);
        fma2(acc2[3][0], a3, b2.x); fma2(acc2[3][1], a3, b2.y);
    }

    // ---- scaled output, float4 coalesced ----
#pragma unroll
    for (int r = 0; r < 4; ++r) {
        int i = ty * 4 + r;
        float f = sfac[i];
        float2 p0 = unpk(acc2[r][0]);
        float2 p1 = unpk(acc2[r][1]);
        float4 o = make_float4(p0.x * f, p0.y * f, p1.x * f, p1.y * f);
        *reinterpret_cast<float4*>(out + base + i * 64 + tx * 4) = o;
    }
}

extern "C" void kernel_launch(void* const* d_in, const int* in_sizes, int n_in,
                              void* d_out, int out_size)
{
    const float* q  = (const float*)d_in[0];
    const float* k  = (const float*)d_in[1];
    const float* v  = (const float*)d_in[2];
    const float* ig = (const float*)d_in[3];
    const float* fg = (const float*)d_in[4];
    float* out = (float*)d_out;

    int nchunks = in_sizes[0] / (LCH * 64);   // B*NH*S*DH / (L*DH) = 2048

    cudaFuncSetAttribute(mlstm_intra_kernel,
                         cudaFuncAttributeMaxDynamicSharedMemorySize, SMEM_BYTES);
    mlstm_intra_kernel<<<nchunks, NTH, SMEM_BYTES>>>(q, k, v, ig, fg, out);
}

// round 3
// speedup vs baseline: 1.2326x; 1.1515x over previous
#include <cuda_runtime.h>
#include <math.h>

#define LCH 64
#define NTH 128
#define SQ 68          // stride of q / S  (mod 32 == 4: 8row x 4col pattern conflict-free)
#define SK 68          // stride of k
#define SV 72          // stride of v      (mod 32 == 8: 4row x 8col pattern conflict-free)

// smem float offsets
#define OFF_Q    0                    // q [64][SQ], overlaid by S after GEMM1
#define OFF_K    (64*SQ)
#define OFF_V    (OFF_K + 64*SK)
#define OFF_SLF  (OFF_V + 64*SV)
#define OFF_SG   (OFF_SLF + 64)
#define OFF_SB   (OFF_SG + 64)
#define OFF_SENC (OFF_SB + 64)
#define OFF_SA   (OFF_SENC + 64)
#define OFF_SFAC (OFF_SA + 64)
#define OFF_RED  (OFF_SFAC + 64)      // [64][2]
#define SMEM_FLOATS (OFF_RED + 128)
#define SMEM_BYTES  (SMEM_FLOATS * 4)

__device__ __forceinline__ void tf32_split(float x, unsigned& hi, unsigned& lo) {
    asm("cvt.rna.tf32.f32 %0, %1;" : "=r"(hi) : "f"(x));
    float fl = x - __uint_as_float(hi);
    asm("cvt.rna.tf32.f32 %0, %1;" : "=r"(lo) : "f"(fl));
}

__device__ __forceinline__ void mma8(float* c, const unsigned* a, const unsigned* b) {
    asm("mma.sync.aligned.m16n8k8.row.col.f32.tf32.tf32.f32 "
        "{%0,%1,%2,%3}, {%4,%5,%6,%7}, {%8,%9}, {%0,%1,%2,%3};"
        : "+f"(c[0]), "+f"(c[1]), "+f"(c[2]), "+f"(c[3])
        : "r"(a[0]), "r"(a[1]), "r"(a[2]), "r"(a[3]), "r"(b[0]), "r"(b[1]));
}

__global__ void __launch_bounds__(NTH, 4) mlstm_intra_kernel(
    const float* __restrict__ q, const float* __restrict__ k,
    const float* __restrict__ v, const float* __restrict__ ig,
    const float* __restrict__ fg, float* __restrict__ out)
{
    extern __shared__ float sm[];
    float* smq  = sm + OFF_Q;
    float* smS  = sm + OFF_Q;    // overlays q after GEMM1
    float* smk  = sm + OFF_K;
    float* smv  = sm + OFF_V;
    float* slf  = sm + OFF_SLF;
    float* sg   = sm + OFF_SG;
    float* sb   = sm + OFF_SB;
    float* senc = sm + OFF_SENC;
    float* sa   = sm + OFF_SA;
    float* sfac = sm + OFF_SFAC;
    float* red  = sm + OFF_RED;

    const int t    = threadIdx.x;
    const int lane = t & 31;
    const int w    = t >> 5;
    const int wy   = w >> 1;          // warp row group: rows 32*wy..32*wy+31
    const int wx   = w & 1;           // warp col group: cols 32*wx..32*wx+31
    const int g    = lane >> 2;       // groupID 0..7
    const int tg   = lane & 3;        // threadID in group
    const int rowA = 32 * wy;
    const int colB = 32 * wx;
    const size_t base = (size_t)blockIdx.x * (LCH * 64);
    const int grow = blockIdx.x * LCH;

    // ---- load q,k,v tiles (row-major, padded strides) ----
    {
        const int lr = t >> 1;            // row 0..63
        const int lh = (t & 1) * 32;      // col base 0/32
        const float4* q4 = reinterpret_cast<const float4*>(q + base + lr * 64 + lh);
        const float4* k4 = reinterpret_cast<const float4*>(k + base + lr * 64 + lh);
        const float4* v4 = reinterpret_cast<const float4*>(v + base + lr * 64 + lh);
#pragma unroll
        for (int c = 0; c < 8; ++c) {
            *reinterpret_cast<float4*>(&smq[lr * SQ + lh + 4 * c]) = q4[c];
            *reinterpret_cast<float4*>(&smk[lr * SK + lh + 4 * c]) = k4[c];
            *reinterpret_cast<float4*>(&smv[lr * SV + lh + 4 * c]) = v4[c];
        }
    }

    // ---- gates (threads 0..63) ----
    float xi = 0.0f;
    if (t < LCH) {
        float xf = fg[grow + t];
        xi = ig[grow + t];
        slf[t] = fminf(xf, 0.0f) - log1pf(__expf(-fabsf(xf)));
    }
    __syncthreads();

    if (t < LCH) {
        float cum = 0.0f;
#pragma unroll 8
        for (int j = 0; j < LCH; ++j) {
            float lv = slf[j];
            if (j <= t) cum += lv;
        }
        float gval = xi - cum;
        sg[t] = gval;
        senc[t] = __expf(-cum);
        sb[t] = __expf(gval) * 0.125f;    // b[j] * 1/sqrt(64)
    }
    __syncthreads();

    if (t < LCH) {
        float M = -INFINITY;
#pragma unroll 8
        for (int j = 0; j < LCH; ++j) {
            float gv = sg[j];
            if (j <= t) M = fmaxf(M, gv);
        }
        sa[t] = __expf(-M);
    }
    __syncthreads();

    // ---- GEMM1: raw scores q.k^T via 3xTF32 mma ----
    float cacc[2][4][4];
#pragma unroll
    for (int mt = 0; mt < 2; ++mt)
#pragma unroll
        for (int nt = 0; nt < 4; ++nt)
#pragma unroll
            for (int e = 0; e < 4; ++e) cacc[mt][nt][e] = 0.0f;

    if (wx <= wy) {   // warp (0,1) is fully above the diagonal: skip
#pragma unroll
        for (int kt = 0; kt < 8; ++kt) {
            const int kb = kt * 8;
            unsigned ahi[2][4], alo[2][4];
#pragma unroll
            for (int mt = 0; mt < 2; ++mt) {
                int r0 = rowA + 16 * mt + g;
                tf32_split(smq[r0 * SQ + kb + tg],           ahi[mt][0], alo[mt][0]);
                tf32_split(smq[(r0 + 8) * SQ + kb + tg],     ahi[mt][1], alo[mt][1]);
                tf32_split(smq[r0 * SQ + kb + tg + 4],       ahi[mt][2], alo[mt][2]);
                tf32_split(smq[(r0 + 8) * SQ + kb + tg + 4], ahi[mt][3], alo[mt][3]);
            }
#pragma unroll
            for (int nt = 0; nt < 4; ++nt) {
                const int nb = colB + 8 * nt;
                if (nb <= rowA + 31) {
                    unsigned bhi[2], blo[2];
                    tf32_split(smk[(nb + g) * SK + kb + tg],     bhi[0], blo[0]);
                    tf32_split(smk[(nb + g) * SK + kb + tg + 4], bhi[1], blo[1]);
#pragma unroll
                    for (int mt = 0; mt < 2; ++mt) {
                        if (nb <= rowA + 16 * mt + 15) {
                            mma8(cacc[mt][nt], alo[mt], bhi);
                            mma8(cacc[mt][nt], ahi[mt], blo);
                            mma8(cacc[mt][nt], ahi[mt], bhi);
                        }
                    }
                }
            }
        }
    }
    __syncthreads();    // all q reads done; S may overlay

    // ---- epilogue: mask, scale by b[j], store S, in-fragment row sums ----
    {
        float rs[4] = {0.0f, 0.0f, 0.0f, 0.0f};
#pragma unroll
        for (int mt = 0; mt < 2; ++mt) {
#pragma unroll
            for (int nt = 0; nt < 4; ++nt) {
                int r0 = rowA + 16 * mt + g;
                int jb = colB + 8 * nt + 2 * tg;
                float sb0 = sb[jb], sb1 = sb[jb + 1];
                float v00 = (jb     <= r0    ) ? cacc[mt][nt][0] * sb0 : 0.0f;
                float v01 = (jb + 1 <= r0    ) ? cacc[mt][nt][1] * sb1 : 0.0f;
                float v10 = (jb     <= r0 + 8) ? cacc[mt][nt][2] * sb0 : 0.0f;
                float v11 = (jb + 1 <= r0 + 8) ? cacc[mt][nt][3] * sb1 : 0.0f;
                *reinterpret_cast<float2*>(&smS[r0 * SQ + jb])       = make_float2(v00, v01);
                *reinterpret_cast<float2*>(&smS[(r0 + 8) * SQ + jb]) = make_float2(v10, v11);
                rs[2 * mt]     += v00 + v01;
                rs[2 * mt + 1] += v10 + v11;
            }
        }
#pragma unroll
        for (int e = 0; e < 4; ++e) {
            rs[e] += __shfl_xor_sync(0xffffffffu, rs[e], 1);
            rs[e] += __shfl_xor_sync(0xffffffffu, rs[e], 2);
        }
        if (tg == 0) {
#pragma unroll
            for (int mt = 0; mt < 2; ++mt) {
                red[(rowA + 16 * mt + g) * 2 + wx]     = rs[2 * mt];
                red[(rowA + 16 * mt + 8 + g) * 2 + wx] = rs[2 * mt + 1];
            }
        }
    }
    __syncthreads();

    // ---- normalizer (threads 0..63) ----
    if (t < LCH) {
        float rsum = red[t * 2] + red[t * 2 + 1];
        float t1 = fmaxf(fabsf(rsum), senc[t]);
        float a_ = sa[t];
        sfac[t] = a_ / fmaf(a_, t1, 1e-6f);
    }
    __syncthreads();

    // ---- GEMM2: H = S.V via 3xTF32 mma (skip k-tiles where S is zero) ----
    float c2[2][4][4];
#pragma unroll
    for (int mt = 0; mt < 2; ++mt)
#pragma unroll
        for (int nt = 0; nt < 4; ++nt)
#pragma unroll
            for (int e = 0; e < 4; ++e) c2[mt][nt][e] = 0.0f;

#pragma unroll
    for (int kt = 0; kt < 8; ++kt) {
        const int kb = kt * 8;
        if (kb <= rowA + 31) {   // S[i][j]=0 for j>i; rows of this warp are <= rowA+31
            unsigned ahi[2][4], alo[2][4];
#pragma unroll
            for (int mt = 0; mt < 2; ++mt) {
                int r0 = rowA + 16 * mt + g;
                tf32_split(smS[r0 * SQ + kb + tg],           ahi[mt][0], alo[mt][0]);
                tf32_split(smS[(r0 + 8) * SQ + kb + tg],     ahi[mt][1], alo[mt][1]);
                tf32_split(smS[r0 * SQ + kb + tg + 4],       ahi[mt][2], alo[mt][2]);
                tf32_split(smS[(r0 + 8) * SQ + kb + tg + 4], ahi[mt][3], alo[mt][3]);
            }
#pragma unroll
            for (int nt = 0; nt < 4; ++nt) {
                const int nb = colB + 8 * nt;
                unsigned bhi[2], blo[2];
                tf32_split(smv[(kb + tg) * SV + nb + g],       bhi[0], blo[0]);
                tf32_split(smv[(kb + tg + 4) * SV + nb + g],   bhi[1], blo[1]);
#pragma unroll
                for (int mt = 0; mt < 2; ++mt) {
                    mma8(c2[mt][nt], alo[mt], bhi);
                    mma8(c2[mt][nt], ahi[mt], blo);
                    mma8(c2[mt][nt], ahi[mt], bhi);
                }
            }
        }
    }

    // ---- scaled output straight from fragments (64-bit stores) ----
#pragma unroll
    for (int mt = 0; mt < 2; ++mt) {
        int r0 = rowA + 16 * mt + g;
        float f0 = sfac[r0], f1 = sfac[r0 + 8];
#pragma unroll
        for (int nt = 0; nt < 4; ++nt) {
            int jb = colB + 8 * nt + 2 * tg;
            *reinterpret_cast<float2*>(out + base + r0 * 64 + jb) =
                make_float2(c2[mt][nt][0] * f0, c2[mt][nt][1] * f0);
            *reinterpret_cast<float2*>(out + base + (r0 + 8) * 64 + jb) =
                make_float2(c2[mt][nt][2] * f1, c2[mt][nt][3] * f1);
        }
    }
}

extern "C" void kernel_launch(void* const* d_in, const int* in_sizes, int n_in,
                              void* d_out, int out_size)
{
    const float* q  = (const float*)d_in[0];
    const float* k  = (const float*)d_in[1];
    const float* v  = (const float*)d_in[2];
    const float* ig = (const float*)d_in[3];
    const float* fg = (const float*)d_in[4];
    float* out = (float*)d_out;

    int nchunks = in_sizes[0] / (LCH * 64);   // 2048

    cudaFuncSetAttribute(mlstm_intra_kernel,
                         cudaFuncAttributeMaxDynamicSharedMemorySize, SMEM_BYTES);
    mlstm_intra_kernel<<<nchunks, NTH, SMEM_BYTES>>>(q, k, v, ig, fg, out);
}

// round 4
// speedup vs baseline: 1.7218x; 1.3968x over previous
#include <cuda_runtime.h>
#include <math.h>

#define LCH 64
#define NTH 256
#define SQ 68          // stride of q / S  (mod 32 == 4)
#define SK 68          // stride of k
#define SV 72          // stride of v      (mod 32 == 8)

// smem float offsets
#define OFF_Q    0                    // q [64][SQ], overlaid by S after GEMM1
#define OFF_K    (64*SQ)
#define OFF_V    (OFF_K + 64*SK)
#define OFF_SLF  (OFF_V + 64*SV)
#define OFF_SG   (OFF_SLF + 64)
#define OFF_SB   (OFF_SG + 64)
#define OFF_SENC (OFF_SB + 64)
#define OFF_SA   (OFF_SENC + 64)
#define OFF_SFAC (OFF_SA + 64)
#define OFF_RED  (OFF_SFAC + 64)      // [64][4]
#define SMEM_FLOATS (OFF_RED + 256)
#define SMEM_BYTES  (SMEM_FLOATS * 4)

__device__ __forceinline__ void tf32_split(float x, unsigned& hi, unsigned& lo) {
    asm("cvt.rna.tf32.f32 %0, %1;" : "=r"(hi) : "f"(x));
    float fl = x - __uint_as_float(hi);
    asm("cvt.rna.tf32.f32 %0, %1;" : "=r"(lo) : "f"(fl));
}

__device__ __forceinline__ void mma8(float* c, const unsigned* a, const unsigned* b) {
    asm("mma.sync.aligned.m16n8k8.row.col.f32.tf32.tf32.f32 "
        "{%0,%1,%2,%3}, {%4,%5,%6,%7}, {%8,%9}, {%0,%1,%2,%3};"
        : "+f"(c[0]), "+f"(c[1]), "+f"(c[2]), "+f"(c[3])
        : "r"(a[0]), "r"(a[1]), "r"(a[2]), "r"(a[3]), "r"(b[0]), "r"(b[1]));
}

__global__ void __launch_bounds__(NTH, 4) mlstm_intra_kernel(
    const float* __restrict__ q, const float* __restrict__ k,
    const float* __restrict__ v, const float* __restrict__ ig,
    const float* __restrict__ fg, float* __restrict__ out)
{
    extern __shared__ float sm[];
    float* smq  = sm + OFF_Q;
    float* smS  = sm + OFF_Q;    // overlays q after GEMM1
    float* smk  = sm + OFF_K;
    float* smv  = sm + OFF_V;
    float* slf  = sm + OFF_SLF;
    float* sg   = sm + OFF_SG;
    float* sb   = sm + OFF_SB;
    float* senc = sm + OFF_SENC;
    float* sa   = sm + OFF_SA;
    float* sfac = sm + OFF_SFAC;
    float* red  = sm + OFF_RED;

    const int t    = threadIdx.x;
    const int lane = t & 31;
    const int w    = t >> 5;          // 0..7
    const int wy   = w >> 2;          // 0..1 : rows 32*wy .. 32*wy+31
    const int wx   = w & 3;           // 0..3 : cols 16*wx .. 16*wx+15
    const int g    = lane >> 2;       // 0..7
    const int tg   = lane & 3;        // 0..3
    const int rowA = 32 * wy;
    const int colB = 16 * wx;
    const size_t base = (size_t)blockIdx.x * (LCH * 64);
    const int grow = blockIdx.x * LCH;

    // ---- load q,k,v tiles: 256 threads, 16 floats/tensor each ----
    {
        const int lr = t >> 2;            // row 0..63
        const int lh = (t & 3) * 16;      // col base 0/16/32/48
        const float4* q4 = reinterpret_cast<const float4*>(q + base + lr * 64 + lh);
        const float4* k4 = reinterpret_cast<const float4*>(k + base + lr * 64 + lh);
        const float4* v4 = reinterpret_cast<const float4*>(v + base + lr * 64 + lh);
#pragma unroll
        for (int c = 0; c < 4; ++c) {
            *reinterpret_cast<float4*>(&smq[lr * SQ + lh + 4 * c]) = q4[c];
            *reinterpret_cast<float4*>(&smk[lr * SK + lh + 4 * c]) = k4[c];
            *reinterpret_cast<float4*>(&smv[lr * SV + lh + 4 * c]) = v4[c];
        }
    }

    // ---- gates (threads 0..63) ----
    float xi = 0.0f;
    if (t < LCH) {
        float xf = fg[grow + t];
        xi = ig[grow + t];
        slf[t] = fminf(xf, 0.0f) - log1pf(__expf(-fabsf(xf)));
    }
    __syncthreads();

    if (t < LCH) {
        float cum = 0.0f;
#pragma unroll 8
        for (int j = 0; j < LCH; ++j) {
            float lv = slf[j];
            if (j <= t) cum += lv;
        }
        float gval = xi - cum;
        sg[t] = gval;
        senc[t] = __expf(-cum);
        sb[t] = __expf(gval) * 0.125f;    // b[j] * 1/sqrt(64)
    }
    __syncthreads();

    if (t < LCH) {
        float M = -INFINITY;
#pragma unroll 8
        for (int j = 0; j < LCH; ++j) {
            float gv = sg[j];
            if (j <= t) M = fmaxf(M, gv);
        }
        sa[t] = __expf(-M);
    }
    __syncthreads();

    // ---- GEMM1: raw scores q.k^T via 3xTF32 mma ----
    float cacc[2][2][4];
#pragma unroll
    for (int mt = 0; mt < 2; ++mt)
#pragma unroll
        for (int nt = 0; nt < 2; ++nt)
#pragma unroll
            for (int e = 0; e < 4; ++e) cacc[mt][nt][e] = 0.0f;

    if (colB <= rowA + 31) {   // warps fully above the diagonal skip
#pragma unroll
        for (int kt = 0; kt < 8; ++kt) {
            const int kb = kt * 8;
            unsigned ahi[2][4], alo[2][4];
#pragma unroll
            for (int mt = 0; mt < 2; ++mt) {
                int r0 = rowA + 16 * mt + g;
                tf32_split(smq[r0 * SQ + kb + tg],           ahi[mt][0], alo[mt][0]);
                tf32_split(smq[(r0 + 8) * SQ + kb + tg],     ahi[mt][1], alo[mt][1]);
                tf32_split(smq[r0 * SQ + kb + tg + 4],       ahi[mt][2], alo[mt][2]);
                tf32_split(smq[(r0 + 8) * SQ + kb + tg + 4], ahi[mt][3], alo[mt][3]);
            }
#pragma unroll
            for (int nt = 0; nt < 2; ++nt) {
                const int nb = colB + 8 * nt;
                if (nb <= rowA + 31) {
                    unsigned bhi[2], blo[2];
                    tf32_split(smk[(nb + g) * SK + kb + tg],     bhi[0], blo[0]);
                    tf32_split(smk[(nb + g) * SK + kb + tg + 4], bhi[1], blo[1]);
#pragma unroll
                    for (int mt = 0; mt < 2; ++mt) {
                        if (nb <= rowA + 16 * mt + 15) {
                            mma8(cacc[mt][nt], alo[mt], bhi);
                            mma8(cacc[mt][nt], ahi[mt], blo);
                            mma8(cacc[mt][nt], ahi[mt], bhi);
                        }
                    }
                }
            }
        }
    }
    __syncthreads();    // all q reads done; S may overlay

    // ---- epilogue: mask, scale by b[j], store S, in-fragment row sums ----
    {
        float rs[4] = {0.0f, 0.0f, 0.0f, 0.0f};
#pragma unroll
        for (int mt = 0; mt < 2; ++mt) {
#pragma unroll
            for (int nt = 0; nt < 2; ++nt) {
                int r0 = rowA + 16 * mt + g;
                int jb = colB + 8 * nt + 2 * tg;
                float sb0 = sb[jb], sb1 = sb[jb + 1];
                float v00 = (jb     <= r0    ) ? cacc[mt][nt][0] * sb0 : 0.0f;
                float v01 = (jb + 1 <= r0    ) ? cacc[mt][nt][1] * sb1 : 0.0f;
                float v10 = (jb     <= r0 + 8) ? cacc[mt][nt][2] * sb0 : 0.0f;
                float v11 = (jb + 1 <= r0 + 8) ? cacc[mt][nt][3] * sb1 : 0.0f;
                *reinterpret_cast<float2*>(&smS[r0 * SQ + jb])       = make_float2(v00, v01);
                *reinterpret_cast<float2*>(&smS[(r0 + 8) * SQ + jb]) = make_float2(v10, v11);
                rs[2 * mt]     += v00 + v01;
                rs[2 * mt + 1] += v10 + v11;
            }
        }
#pragma unroll
        for (int e = 0; e < 4; ++e) {
            rs[e] += __shfl_xor_sync(0xffffffffu, rs[e], 1);
            rs[e] += __shfl_xor_sync(0xffffffffu, rs[e], 2);
        }
        if (tg == 0) {
#pragma unroll
            for (int mt = 0; mt < 2; ++mt) {
                red[(rowA + 16 * mt + g) * 4 + wx]     = rs[2 * mt];
                red[(rowA + 16 * mt + 8 + g) * 4 + wx] = rs[2 * mt + 1];
            }
        }
    }
    __syncthreads();

    // ---- normalizer (threads 0..63) ----
    if (t < LCH) {
        float rsum = (red[t * 4] + red[t * 4 + 1]) + (red[t * 4 + 2] + red[t * 4 + 3]);
        float t1 = fmaxf(fabsf(rsum), senc[t]);
        float a_ = sa[t];
        sfac[t] = a_ / fmaf(a_, t1, 1e-6f);
    }
    __syncthreads();

    // ---- GEMM2: H = S.V via 3xTF32 mma (skip zero k-tiles) ----
    float c2[2][2][4];
#pragma unroll
    for (int mt = 0; mt < 2; ++mt)
#pragma unroll
        for (int nt = 0; nt < 2; ++nt)
#pragma unroll
            for (int e = 0; e < 4; ++e) c2[mt][nt][e] = 0.0f;

#pragma unroll
    for (int kt = 0; kt < 8; ++kt) {
        const int kb = kt * 8;
        if (kb <= rowA + 31) {   // S[i][j]=0 for j>i
            unsigned ahi[2][4], alo[2][4];
#pragma unroll
            for (int mt = 0; mt < 2; ++mt) {
                int r0 = rowA + 16 * mt + g;
                tf32_split(smS[r0 * SQ + kb + tg],           ahi[mt][0], alo[mt][0]);
                tf32_split(smS[(r0 + 8) * SQ + kb + tg],     ahi[mt][1], alo[mt][1]);
                tf32_split(smS[r0 * SQ + kb + tg + 4],       ahi[mt][2], alo[mt][2]);
                tf32_split(smS[(r0 + 8) * SQ + kb + tg + 4], ahi[mt][3], alo[mt][3]);
            }
#pragma unroll
            for (int nt = 0; nt < 2; ++nt) {
                const int nb = colB + 8 * nt;
                unsigned bhi[2], blo[2];
                tf32_split(smv[(kb + tg) * SV + nb + g],       bhi[0], blo[0]);
                tf32_split(smv[(kb + tg + 4) * SV + nb + g],   bhi[1], blo[1]);
#pragma unroll
                for (int mt = 0; mt < 2; ++mt) {
                    mma8(c2[mt][nt], alo[mt], bhi);
                    mma8(c2[mt][nt], ahi[mt], blo);
                    mma8(c2[mt][nt], ahi[mt], bhi);
                }
            }
        }
    }

    // ---- scaled output straight from fragments (64-bit stores) ----
#pragma unroll
    for (int mt = 0; mt < 2; ++mt) {
        int r0 = rowA + 16 * mt + g;
        float f0 = sfac[r0], f1 = sfac[r0 + 8];
#pragma unroll
        for (int nt = 0; nt < 2; ++nt) {
            int jb = colB + 8 * nt + 2 * tg;
            *reinterpret_cast<float2*>(out + base + r0 * 64 + jb) =
                make_float2(c2[mt][nt][0] * f0, c2[mt][nt][1] * f0);
            *reinterpret_cast<float2*>(out + base + (r0 + 8) * 64 + jb) =
                make_float2(c2[mt][nt][2] * f1, c2[mt][nt][3] * f1);
        }
    }
}

extern "C" void kernel_launch(void* const* d_in, const int* in_sizes, int n_in,
                              void* d_out, int out_size)
{
    const float* q  = (const float*)d_in[0];
    const float* k  = (const float*)d_in[1];
    const float* v  = (const float*)d_in[2];
    const float* ig = (const float*)d_in[3];
    const float* fg = (const float*)d_in[4];
    float* out = (float*)d_out;

    int nchunks = in_sizes[0] / (LCH * 64);   // 2048

    cudaFuncSetAttribute(mlstm_intra_kernel,
                         cudaFuncAttributeMaxDynamicSharedMemorySize, SMEM_BYTES);
    mlstm_intra_kernel<<<nchunks, NTH, SMEM_BYTES>>>(q, k, v, ig, fg, out);
}

// round 5
// speedup vs baseline: 2.5080x; 1.4566x over previous
#include <cuda_runtime.h>
#include <math.h>

#define LCH 64
#define NTH 256
#define SQW 36          // q/S plane row stride in words (bank-bijective: 4g+tg)
#define SVW 68          // v plane row stride in words

// smem word offsets
#define QH0   0         // q hi plane [64][SQW] (2304 w), overlaid by S hi after GEMM1
#define QL0   2304      // q lo plane / S lo
#define KH0   4608
#define KL0   6912
#define VH0   9216      // v hi plane [32 j-pairs][SVW] (2176 w)
#define VL0   11392
#define GOFF  13568
#define SMEM_WORDS 14208
#define SMEM_BYTES (SMEM_WORDS * 4)

// split x into bf16 hi + bf16 lo planes, packed pairwise:
// word = {upper: elem1, lower: elem0}  (PTX cvt: first src -> upper)
__device__ __forceinline__ void split_pair(float x0, float x1, unsigned& hw, unsigned& lw) {
    asm("cvt.rn.bf16x2.f32 %0, %1, %2;" : "=r"(hw) : "f"(x1), "f"(x0));
    float h0 = __uint_as_float(hw << 16);
    float h1 = __uint_as_float(hw & 0xFFFF0000u);
    float r0 = x0 - h0;
    float r1 = x1 - h1;
    asm("cvt.rn.bf16x2.f32 %0, %1, %2;" : "=r"(lw) : "f"(r1), "f"(r0));
}

__device__ __forceinline__ void mma16(float* c, const unsigned* a, const unsigned* b) {
    asm("mma.sync.aligned.m16n8k16.row.col.f32.bf16.bf16.f32 "
        "{%0,%1,%2,%3}, {%4,%5,%6,%7}, {%8,%9}, {%0,%1,%2,%3};"
        : "+f"(c[0]), "+f"(c[1]), "+f"(c[2]), "+f"(c[3])
        : "r"(a[0]), "r"(a[1]), "r"(a[2]), "r"(a[3]), "r"(b[0]), "r"(b[1]));
}

__global__ void __launch_bounds__(NTH, 4) mlstm_intra_kernel(
    const float* __restrict__ q, const float* __restrict__ k,
    const float* __restrict__ v, const float* __restrict__ ig,
    const float* __restrict__ fg, float* __restrict__ out)
{
    extern __shared__ unsigned smu[];
    unsigned* QH = smu + QH0;   // also S hi after GEMM1
    unsigned* QL = smu + QL0;   // also S lo
    unsigned* KH = smu + KH0;
    unsigned* KL = smu + KL0;
    unsigned* VH = smu + VH0;
    unsigned* VL = smu + VL0;
    float* slf  = reinterpret_cast<float*>(smu + GOFF);
    float* sg   = slf + 64;
    float* sb   = slf + 128;
    float* senc = slf + 192;
    float* sa   = slf + 256;
    float* sfac = slf + 320;
    float* red  = slf + 384;     // [64][4]

    const int t    = threadIdx.x;
    const int lane = t & 31;
    const int w    = t >> 5;          // 0..7
    const int wy   = w >> 2;          // rows 32*wy .. +31
    const int wx   = w & 3;           // cols 16*wx .. +15
    const int g    = lane >> 2;       // 0..7
    const int tg   = lane & 3;        // 0..3
    const int rowA = 32 * wy;
    const int colB = 16 * wx;
    const size_t base = (size_t)blockIdx.x * (LCH * 64);
    const int grow = blockIdx.x * LCH;

    // ---- load + split q,k (row-major planes) ----
    {
        const int lr = t >> 2;            // row 0..63
        const int lq = t & 3;             // col block: 16 floats
        const float4* q4 = reinterpret_cast<const float4*>(q + base + lr * 64 + 16 * lq);
        const float4* k4 = reinterpret_cast<const float4*>(k + base + lr * 64 + 16 * lq);
        unsigned qh[8], ql[8], kh[8], kl[8];
#pragma unroll
        for (int c = 0; c < 4; ++c) {
            float4 wq = q4[c];
            float4 wk = k4[c];
            split_pair(wq.x, wq.y, qh[2 * c],     ql[2 * c]);
            split_pair(wq.z, wq.w, qh[2 * c + 1], ql[2 * c + 1]);
            split_pair(wk.x, wk.y, kh[2 * c],     kl[2 * c]);
            split_pair(wk.z, wk.w, kh[2 * c + 1], kl[2 * c + 1]);
        }
        unsigned* qhp = QH + lr * SQW + 8 * lq;
        unsigned* qlp = QL + lr * SQW + 8 * lq;
        unsigned* khp = KH + lr * SQW + 8 * lq;
        unsigned* klp = KL + lr * SQW + 8 * lq;
        *reinterpret_cast<uint4*>(qhp)     = make_uint4(qh[0], qh[1], qh[2], qh[3]);
        *reinterpret_cast<uint4*>(qhp + 4) = make_uint4(qh[4], qh[5], qh[6], qh[7]);
        *reinterpret_cast<uint4*>(qlp)     = make_uint4(ql[0], ql[1], ql[2], ql[3]);
        *reinterpret_cast<uint4*>(qlp + 4) = make_uint4(ql[4], ql[5], ql[6], ql[7]);
        *reinterpret_cast<uint4*>(khp)     = make_uint4(kh[0], kh[1], kh[2], kh[3]);
        *reinterpret_cast<uint4*>(khp + 4) = make_uint4(kh[4], kh[5], kh[6], kh[7]);
        *reinterpret_cast<uint4*>(klp)     = make_uint4(kl[0], kl[1], kl[2], kl[3]);
        *reinterpret_cast<uint4*>(klp + 4) = make_uint4(kl[4], kl[5], kl[6], kl[7]);
    }
    // ---- load + split v: word [j2][d] = {upper: V[2j2+1][d], lower: V[2j2][d]} ----
    {
        const int j2 = t >> 3;            // 0..31
        const int pt = t & 7;             // col block: 8 floats
        const float4* v0 = reinterpret_cast<const float4*>(v + base + (2 * j2) * 64 + 8 * pt);
        const float4* v1 = reinterpret_cast<const float4*>(v + base + (2 * j2 + 1) * 64 + 8 * pt);
        float4 a0 = v0[0], a1 = v0[1], b0 = v1[0], b1 = v1[1];
        float r0[8] = {a0.x, a0.y, a0.z, a0.w, a1.x, a1.y, a1.z, a1.w};
        float r1[8] = {b0.x, b0.y, b0.z, b0.w, b1.x, b1.y, b1.z, b1.w};
        unsigned vh[8], vl[8];
#pragma unroll
        for (int c = 0; c < 8; ++c)
            split_pair(r0[c], r1[c], vh[c], vl[c]);
        unsigned* vhp = VH + j2 * SVW + 8 * pt;
        unsigned* vlp = VL + j2 * SVW + 8 * pt;
        *reinterpret_cast<uint4*>(vhp)     = make_uint4(vh[0], vh[1], vh[2], vh[3]);
        *reinterpret_cast<uint4*>(vhp + 4) = make_uint4(vh[4], vh[5], vh[6], vh[7]);
        *reinterpret_cast<uint4*>(vlp)     = make_uint4(vl[0], vl[1], vl[2], vl[3]);
        *reinterpret_cast<uint4*>(vlp + 4) = make_uint4(vl[4], vl[5], vl[6], vl[7]);
    }

    // ---- gates (threads 0..63) ----
    float xi = 0.0f;
    if (t < LCH) {
        float xf = fg[grow + t];
        xi = ig[grow + t];
        slf[t] = fminf(xf, 0.0f) - log1pf(__expf(-fabsf(xf)));
    }
    __syncthreads();

    if (t < LCH) {
        float cum = 0.0f;
#pragma unroll 8
        for (int j = 0; j < LCH; ++j) {
            float lv = slf[j];
            if (j <= t) cum += lv;
        }
        float gval = xi - cum;
        sg[t] = gval;
        senc[t] = __expf(-cum);
        sb[t] = __expf(gval) * 0.125f;    // b[j] * 1/sqrt(64)
    }
    __syncthreads();

    if (t < LCH) {
        float M = -INFINITY;
#pragma unroll 8
        for (int j = 0; j < LCH; ++j) {
            float gv = sg[j];
            if (j <= t) M = fmaxf(M, gv);
        }
        sa[t] = __expf(-M);
    }
    __syncthreads();

    // ---- GEMM1: raw q.k^T via 2-term bf16 split (3 mmas per k16) ----
    float cacc[2][2][4];
#pragma unroll
    for (int mt = 0; mt < 2; ++mt)
#pragma unroll
        for (int nt = 0; nt < 2; ++nt)
#pragma unroll
            for (int e = 0; e < 4; ++e) cacc[mt][nt][e] = 0.0f;

    if (colB <= rowA + 31) {
#pragma unroll
        for (int kt = 0; kt < 4; ++kt) {
            const int kw = kt * 8;
            unsigned ah[2][4], al[2][4];
#pragma unroll
            for (int mt = 0; mt < 2; ++mt) {
                int r0 = rowA + 16 * mt + g;
                ah[mt][0] = QH[r0 * SQW + kw + tg];
                ah[mt][1] = QH[(r0 + 8) * SQW + kw + tg];
                ah[mt][2] = QH[r0 * SQW + kw + tg + 4];
                ah[mt][3] = QH[(r0 + 8) * SQW + kw + tg + 4];
                al[mt][0] = QL[r0 * SQW + kw + tg];
                al[mt][1] = QL[(r0 + 8) * SQW + kw + tg];
                al[mt][2] = QL[r0 * SQW + kw + tg + 4];
                al[mt][3] = QL[(r0 + 8) * SQW + kw + tg + 4];
            }
#pragma unroll
            for (int nt = 0; nt < 2; ++nt) {
                const int nb = colB + 8 * nt;
                if (nb <= rowA + 31) {
                    unsigned bh[2], bl[2];
                    bh[0] = KH[(nb + g) * SQW + kw + tg];
                    bh[1] = KH[(nb + g) * SQW + kw + tg + 4];
                    bl[0] = KL[(nb + g) * SQW + kw + tg];
                    bl[1] = KL[(nb + g) * SQW + kw + tg + 4];
#pragma unroll
                    for (int mt = 0; mt < 2; ++mt) {
                        if (nb <= rowA + 16 * mt + 15) {
                            mma16(cacc[mt][nt], al[mt], bh);
                            mma16(cacc[mt][nt], ah[mt], bl);
                            mma16(cacc[mt][nt], ah[mt], bh);
                        }
                    }
                }
            }
        }
    }
    __syncthreads();    // all q-plane reads done; S overlays

    // ---- epilogue: mask, scale by b[j], split+store S planes, row sums ----
    {
        float rs[4] = {0.0f, 0.0f, 0.0f, 0.0f};
#pragma unroll
        for (int mt = 0; mt < 2; ++mt) {
#pragma unroll
            for (int nt = 0; nt < 2; ++nt) {
                int r0 = rowA + 16 * mt + g;
                int jb = colB + 8 * nt + 2 * tg;
                int wq = (jb >> 1);
                float sb0 = sb[jb], sb1 = sb[jb + 1];
                float v00 = (jb     <= r0    ) ? cacc[mt][nt][0] * sb0 : 0.0f;
                float v01 = (jb + 1 <= r0    ) ? cacc[mt][nt][1] * sb1 : 0.0f;
                float v10 = (jb     <= r0 + 8) ? cacc[mt][nt][2] * sb0 : 0.0f;
                float v11 = (jb + 1 <= r0 + 8) ? cacc[mt][nt][3] * sb1 : 0.0f;
                unsigned hw, lw;
                split_pair(v00, v01, hw, lw);
                QH[r0 * SQW + wq] = hw;
                QL[r0 * SQW + wq] = lw;
                split_pair(v10, v11, hw, lw);
                QH[(r0 + 8) * SQW + wq] = hw;
                QL[(r0 + 8) * SQW + wq] = lw;
                rs[2 * mt]     += v00 + v01;
                rs[2 * mt + 1] += v10 + v11;
            }
        }
#pragma unroll
        for (int e = 0; e < 4; ++e) {
            rs[e] += __shfl_xor_sync(0xffffffffu, rs[e], 1);
            rs[e] += __shfl_xor_sync(0xffffffffu, rs[e], 2);
        }
        if (tg == 0) {
#pragma unroll
            for (int mt = 0; mt < 2; ++mt) {
                red[(rowA + 16 * mt + g) * 4 + wx]     = rs[2 * mt];
                red[(rowA + 16 * mt + 8 + g) * 4 + wx] = rs[2 * mt + 1];
            }
        }
    }
    __syncthreads();

    // ---- normalizer (threads 0..63) ----
    if (t < LCH) {
        float rsum = (red[t * 4] + red[t * 4 + 1]) + (red[t * 4 + 2] + red[t * 4 + 3]);
        float t1 = fmaxf(fabsf(rsum), senc[t]);
        float a_ = sa[t];
        sfac[t] = a_ / fmaf(a_, t1, 1e-6f);
    }
    __syncthreads();

    // ---- GEMM2: H = S.V (skip k-tiles above the diagonal) ----
    float c2[2][2][4];
#pragma unroll
    for (int mt = 0; mt < 2; ++mt)
#pragma unroll
        for (int nt = 0; nt < 2; ++nt)
#pragma unroll
            for (int e = 0; e < 4; ++e) c2[mt][nt][e] = 0.0f;

#pragma unroll
    for (int kt = 0; kt < 4; ++kt) {
        const int kb = 16 * kt;
        if (kb <= rowA + 31) {
            const int kw = kt * 8;
            unsigned ah[2][4], al[2][4];
#pragma unroll
            for (int mt = 0; mt < 2; ++mt) {
                int r0 = rowA + 16 * mt + g;
                ah[mt][0] = QH[r0 * SQW + kw + tg];        // S hi plane
                ah[mt][1] = QH[(r0 + 8) * SQW + kw + tg];
                ah[mt][2] = QH[r0 * SQW + kw + tg + 4];
                ah[mt][3] = QH[(r0 + 8) * SQW + kw + tg + 4];
                al[mt][0] = QL[r0 * SQW + kw + tg];
                al[mt][1] = QL[(r0 + 8) * SQW + kw + tg];
                al[mt][2] = QL[r0 * SQW + kw + tg + 4];
                al[mt][3] = QL[(r0 + 8) * SQW + kw + tg + 4];
            }
#pragma unroll
            for (int nt = 0; nt < 2; ++nt) {
                const int nb = colB + 8 * nt;
                unsigned bh[2], bl[2];
                bh[0] = VH[(kw + tg) * SVW + nb + g];
                bh[1] = VH[(kw + tg + 4) * SVW + nb + g];
                bl[0] = VL[(kw + tg) * SVW + nb + g];
                bl[1] = VL[(kw + tg + 4) * SVW + nb + g];
#pragma unroll
                for (int mt = 0; mt < 2; ++mt) {
                    mma16(c2[mt][nt], al[mt], bh);
                    mma16(c2[mt][nt], ah[mt], bl);
                    mma16(c2[mt][nt], ah[mt], bh);
                }
            }
        }
    }

    // ---- scaled output straight from fragments ----
#pragma unroll
    for (int mt = 0; mt < 2; ++mt) {
        int r0 = rowA + 16 * mt + g;
        float f0 = sfac[r0], f1 = sfac[r0 + 8];
#pragma unroll
        for (int nt = 0; nt < 2; ++nt) {
            int jb = colB + 8 * nt + 2 * tg;
            *reinterpret_cast<float2*>(out + base + r0 * 64 + jb) =
                make_float2(c2[mt][nt][0] * f0, c2[mt][nt][1] * f0);
            *reinterpret_cast<float2*>(out + base + (r0 + 8) * 64 + jb) =
                make_float2(c2[mt][nt][2] * f1, c2[mt][nt][3] * f1);
        }
    }
}

extern "C" void kernel_launch(void* const* d_in, const int* in_sizes, int n_in,
                              void* d_out, int out_size)
{
    const float* q  = (const float*)d_in[0];
    const float* k  = (const float*)d_in[1];
    const float* v  = (const float*)d_in[2];
    const float* ig = (const float*)d_in[3];
    const float* fg = (const float*)d_in[4];
    float* out = (float*)d_out;

    int nchunks = in_sizes[0] / (LCH * 64);   // 2048

    cudaFuncSetAttribute(mlstm_intra_kernel,
                         cudaFuncAttributeMaxDynamicSharedMemorySize, SMEM_BYTES);
    mlstm_intra_kernel<<<nchunks, NTH, SMEM_BYTES>>>(q, k, v, ig, fg, out);
}